// round 11
// baseline (speedup 1.0000x reference)
#include <cuda_runtime.h>
#include <cstdint>

#define NB   8
#define CIN  64
#define COUT 128
#define HH   32
#define WW   32
#define QWN  (COUT*144)            // 18432 int32 words of packed B

#define BOFF   0
#define BROW   592                 // 576+16 pad (37*16B, odd) -> conflict-free ldmatrix
#define BSZ    (COUT*BROW)         // 75776
#define HALO   BSZ                 // float halo: 136 pixels x 65 floats (odd stride) = 35360 B
#define HSTR   65
#define STAGE  (HALO + 136*HSTR*4) // 111136: int8 staging, 136 pixels x 80 B
#define PIXSTR 80
#define WROW   (STAGE + 136*PIXSTR)// 122016: w-row floats (576)
#define SMEM_SZ (WROW + 576*4)     // 124320

#define NCTA 128
#define NTHR 512

// ---------------- scratch (device globals; no allocation) ----------------
__device__ unsigned g_partx[NCTA];
__device__ unsigned g_partw[NCTA];
__device__ int      g_wpack[QWN];         // [co][tap][c4w]
__device__ unsigned g_barX = 0u;          // monotonic grid-barrier counters
__device__ unsigned g_barW = 0u;          // (never reset; group = next multiple of 128)
__device__ unsigned g_barB = 0u;

__device__ __forceinline__ uint32_t smem_u32(const void* p) {
    uint32_t a;
    asm("{ .reg .u64 t; cvta.to.shared.u64 t, %1; cvt.u32.u64 %0, t; }" : "=r"(a) : "l"(p));
    return a;
}

#define LDSM_X4(r0, r1, r2, r3, a) \
    asm volatile("ldmatrix.sync.aligned.m8n8.x4.shared.b16 {%0,%1,%2,%3}, [%4];" \
                 : "=r"(r0), "=r"(r1), "=r"(r2), "=r"(r3) : "r"(a))

#define IMMA(c, a0, a1, a2, a3, b0, b1) \
    asm volatile("mma.sync.aligned.m16n8k32.row.col.s32.s8.s8.s32 " \
                 "{%0,%1,%2,%3}, {%4,%5,%6,%7}, {%8,%9}, {%0,%1,%2,%3};" \
                 : "+r"((c)[0]), "+r"((c)[1]), "+r"((c)[2]), "+r"((c)[3]) \
                 : "r"(a0), "r"(a1), "r"(a2), "r"(a3), "r"(b0), "r"(b1))

#define GBAR(id, n) asm volatile("bar.sync %0, %1;" :: "r"(id), "r"(n) : "memory")

__device__ __forceinline__ int quant(float v, float s) {
    float r = rintf(__fmul_rn(v, s));      // round half-to-even == jnp.round
    r = fminf(fmaxf(r, -128.0f), 127.0f);
    return (int)r;
}

// single-thread arrive+wait on a monotonic 128-CTA barrier (all CTAs co-resident)
__device__ __forceinline__ void bar_arrive_wait(unsigned* bar) {
    __threadfence();
    unsigned ticket = atomicAdd(bar, 1u);
    unsigned target = (ticket & ~127u) + 128u;
    unsigned v;
    do {
        asm volatile("ld.acquire.gpu.u32 %0, [%1];" : "=r"(v) : "l"(bar) : "memory");
    } while ((int)(v - target) < 0);
}

// ---------------- ONE fused kernel, dual warp-specialized pipelines ----------------
__global__ void __launch_bounds__(NTHR, 1)
k_fused(const float* __restrict__ x, const float* __restrict__ w,
        const float* __restrict__ bias,
        const float* __restrict__ Tf_in, const float* __restrict__ Tw_in,
        float* __restrict__ out) {
    extern __shared__ char sm[];
    __shared__ unsigned sredx[8], sredw[8];
    __shared__ float s_sc[3], s_T[2];

    const int t = threadIdx.x, wid = t >> 5, lane = t & 31;
    const int b  = blockIdx.x >> 4;
    const int y0 = (blockIdx.x & 15) * 2;

    float* __restrict__ halo = (float*)(sm + HALO);
    float* __restrict__ wrow = (float*)(sm + WROW);

    if (wid < 8) {
        // ================= x-path: warps 0-7 (256 threads) =================
        unsigned mx = 0u;
        #pragma unroll 17
        for (int k = 0; k < 34; ++k) {         // 34*256 = 8704 = 136 pix * 64 ch
            int i = t + k*256;
            int pix = i % 136, ch = i / 136;
            int sc = pix % 34, sr = pix / 34;
            int R  = y0 + sr;                   // padded row
            float v = 0.0f;
            if (R >= 1 && R <= HH && sc >= 1 && sc <= WW)
                v = x[((b*CIN + ch)*HH + (R - 1))*WW + (sc - 1)];
            halo[pix*HSTR + ch] = v;
            mx = max(mx, __float_as_uint(fabsf(v)));
        }
        #pragma unroll
        for (int o = 16; o; o >>= 1) mx = max(mx, __shfl_xor_sync(0xffffffffu, mx, o));
        if (lane == 0) sredx[wid] = mx;
        GBAR(1, 256);
        if (t < 32) {
            unsigned m2 = (lane < 8) ? sredx[lane] : 0u;
            #pragma unroll
            for (int o = 4; o; o >>= 1) m2 = max(m2, __shfl_xor_sync(0xffffffffu, m2, o));
            if (t == 0) {
                g_partx[blockIdx.x] = m2;
                bar_arrive_wait(&g_barX);
            }
        }
        GBAR(1, 256);
        if (t < 32) {
            unsigned vx = max(max(g_partx[lane], g_partx[lane + 32]),
                              max(g_partx[lane + 64], g_partx[lane + 96]));
            #pragma unroll
            for (int o = 16; o; o >>= 1) vx = max(vx, __shfl_xor_sync(0xffffffffu, vx, o));
            if (t == 0) {
                float Tf = __fadd_rn(__fmul_rn(0.95f, Tf_in[0]),
                                     __fmul_rn(0.05f, __uint_as_float(vx)));
                s_T[0] = Tf;
                s_sc[0] = __fdiv_rn(127.0f, Tf);
            }
        }
        GBAR(1, 256);
        // quantize halo -> int8 staging (544 items over 256 threads)
        {
            const float sf = s_sc[0];
            #pragma unroll
            for (int k = 0; k < 3; ++k) {
                int i = t + k*256;
                if (i < 544) {
                    int pix = i % 136, c4 = i / 136;
                    const float* hp = halo + pix*HSTR + c4*16;
                    int q[16];
                    #pragma unroll
                    for (int j = 0; j < 16; ++j)
                        q[j] = quant(hp[j], sf) & 255;
                    int4 v;
                    v.x = q[0]  | (q[1]  << 8) | (q[2]  << 16) | (q[3]  << 24);
                    v.y = q[4]  | (q[5]  << 8) | (q[6]  << 16) | (q[7]  << 24);
                    v.z = q[8]  | (q[9]  << 8) | (q[10] << 16) | (q[11] << 24);
                    v.w = q[12] | (q[13] << 8) | (q[14] << 16) | (q[15] << 24);
                    *(int4*)(sm + STAGE + pix*PIXSTR + c4*16) = v;
                }
            }
        }
    } else {
        // ================= w-path: warps 8-15 (256 threads) =================
        const int tw = t - 256;
        unsigned mw;
        {
            float wv0 = w[blockIdx.x*576 + tw];
            float wv1 = w[blockIdx.x*576 + 256 + tw];
            wrow[tw] = wv0;
            wrow[256 + tw] = wv1;
            mw = max(__float_as_uint(fabsf(wv0)), __float_as_uint(fabsf(wv1)));
            if (tw < 64) {
                float wv2 = w[blockIdx.x*576 + 512 + tw];
                wrow[512 + tw] = wv2;
                mw = max(mw, __float_as_uint(fabsf(wv2)));
            }
        }
        #pragma unroll
        for (int o = 16; o; o >>= 1) mw = max(mw, __shfl_xor_sync(0xffffffffu, mw, o));
        if (lane == 0) sredw[wid - 8] = mw;
        GBAR(2, 256);
        if (tw < 32) {
            unsigned m2 = (lane < 8) ? sredw[lane] : 0u;
            #pragma unroll
            for (int o = 4; o; o >>= 1) m2 = max(m2, __shfl_xor_sync(0xffffffffu, m2, o));
            if (tw == 0) {
                g_partw[blockIdx.x] = m2;
                bar_arrive_wait(&g_barW);
            }
        }
        GBAR(2, 256);
        if (tw < 32) {
            unsigned vw = max(max(g_partw[lane], g_partw[lane + 32]),
                              max(g_partw[lane + 64], g_partw[lane + 96]));
            #pragma unroll
            for (int o = 16; o; o >>= 1) vw = max(vw, __shfl_xor_sync(0xffffffffu, vw, o));
            if (tw == 0) {
                float Tw = __fadd_rn(__fmul_rn(0.95f, Tw_in[0]),
                                     __fmul_rn(0.05f, __uint_as_float(vw)));
                s_T[1] = Tw;
                s_sc[1] = __fdiv_rn(127.0f, Tw);
            }
        }
        GBAR(2, 256);
        if (tw < 144) {
            const int tap = tw >> 4, c4w = tw & 15;
            const float sf = s_sc[1];
            int q0 = quant(wrow[(c4w*4 + 0)*9 + tap], sf) & 255;
            int q1 = quant(wrow[(c4w*4 + 1)*9 + tap], sf) & 255;
            int q2 = quant(wrow[(c4w*4 + 2)*9 + tap], sf) & 255;
            int q3 = quant(wrow[(c4w*4 + 3)*9 + tap], sf) & 255;
            g_wpack[blockIdx.x*144 + tw] = q0 | (q1 << 8) | (q2 << 16) | (q3 << 24);
        }
        GBAR(2, 256);
        if (tw == 0) bar_arrive_wait(&g_barB);
        GBAR(2, 256);
        // B-fill: [co][576B] stride 592 (4608 int4 over 256 threads)
        {
            const int4* __restrict__ src = (const int4*)g_wpack;
            int4* __restrict__ Bm = (int4*)(sm + BOFF);
            #pragma unroll
            for (int k = 0; k < 18; ++k) {
                int i = tw + k*256;
                int co = i / 36, j = i % 36;
                Bm[co*37 + j] = src[i];
            }
        }
    }
    __syncthreads();
    if (t == 0)
        s_sc[2] = __fmul_rn(__fdiv_rn(s_T[0], 127.0f), __fdiv_rn(s_T[1], 127.0f));
    __syncthreads();

    // ===== mainloop: 16 warps = 4(M) x 4(N); warp = m16 x n32 =====
    const int wm = (wid & 3) * 16;
    const int wn = (wid >> 2) * 32;
    const uint32_t sbase = smem_u32(sm);

    const int pix = wm + (lane & 15);
    const uint32_t aAddr0 = sbase + STAGE
                          + (uint32_t)(((pix >> 5)*34 + (pix & 31))*PIXSTR)
                          + (uint32_t)(lane >> 4)*16;
    uint32_t bAddr[2];
    #pragma unroll
    for (int np = 0; np < 2; ++np)
        bAddr[np] = sbase + BOFF
                  + (uint32_t)(wn + np*16 + (lane & 7) + ((lane >> 4) & 1)*8)*BROW
                  + (uint32_t)((lane >> 3) & 1)*16;

    int acc[4][4];
    #pragma unroll
    for (int nf = 0; nf < 4; ++nf)
        #pragma unroll
        for (int j = 0; j < 4; ++j) acc[nf][j] = 0;

    #pragma unroll
    for (int ks = 0; ks < 18; ++ks) {
        const int tap = ks >> 1;
        const uint32_t aoff = (uint32_t)(((tap/3)*34 + (tap%3))*PIXSTR + (ks & 1)*32);
        const uint32_t boff = (uint32_t)ks * 32;
        uint32_t a[4], bb[2][4];
        LDSM_X4(a[0], a[1], a[2], a[3], aAddr0 + aoff);
        #pragma unroll
        for (int np = 0; np < 2; ++np)
            LDSM_X4(bb[np][0], bb[np][1], bb[np][2], bb[np][3], bAddr[np] + boff);
        #pragma unroll
        for (int nf = 0; nf < 4; ++nf)
            IMMA(acc[nf], a[0], a[1], a[2], a[3],
                 bb[nf >> 1][(nf & 1)*2], bb[nf >> 1][(nf & 1)*2 + 1]);
    }

    // ===== epilogue: s32 -> f32 * sc + bias =====
    const float sc = s_sc[2];
    const int p0 = wm + (lane >> 2);           // pixel for c0/c1 (c2/c3: +8)
    #pragma unroll
    for (int nf = 0; nf < 4; ++nf) {
        const int co0 = wn + nf*8 + (lane & 3)*2;
        const float b0 = __ldg(&bias[co0]);
        const float b1 = __ldg(&bias[co0 + 1]);
        #pragma unroll
        for (int half = 0; half < 2; ++half) {
            const int p = p0 + half*8;
            const int y = y0 + (p >> 5), xx = p & 31;
            float* po = out + (((size_t)b*COUT + co0)*HH + y)*WW + xx;
            po[0]     = (float)acc[nf][half*2]     * sc + b0;
            po[HH*WW] = (float)acc[nf][half*2 + 1] * sc + b1;
        }
    }
}

// ---------------- launch ----------------
extern "C" void kernel_launch(void* const* d_in, const int* in_sizes, int n_in,
                              void* d_out, int out_size) {
    const float* x    = (const float*)d_in[0];
    const float* w    = (const float*)d_in[1];
    const float* bias = (const float*)d_in[2];
    // d_in[3] = lut (exact a*b -> tensor core), d_in[4] = gradient_lut (unused)
    const float* Tf   = (const float*)d_in[5];
    const float* Tw   = (const float*)d_in[6];
    float* out = (float*)d_out;

    cudaFuncSetAttribute(k_fused, cudaFuncAttributeMaxDynamicSharedMemorySize, SMEM_SZ);
    k_fused<<<NCTA, NTHR, SMEM_SZ>>>(x, w, bias, Tf, Tw, out);
}